// round 2
// baseline (speedup 1.0000x reference)
#include <cuda_runtime.h>

// B=2, H=W=64. grid_dist_tensor: [64,64,64,64] -> 4096 tiles x 4096 floats.
// Key algebraic reduction: all per-(b,h,w) multipliers are non-negative scalars
// w.r.t. the (i,j) min axes, so min(s*dist) = s*min(dist). One min per tile.
// Outputs: [loss | min_dist | min_dist_inv], each [2,64,64] flattened.

#define EPS_F   1e-8f
#define BIG_F   1000000.0f
#define HW      4096
#define BHW     8192
#define TILES_PER_BLOCK 2

__global__ __launch_bounds__(256)
void project_loss_kernel(const float* __restrict__ preds,
                         const float* __restrict__ gts,
                         const float* __restrict__ grid,
                         float* __restrict__ out)
{
    const int tile0 = blockIdx.x * TILES_PER_BLOCK;   // first of 2 tiles
    const int tid   = threadIdx.x;                     // 256 threads

    const float4* ga = reinterpret_cast<const float4*>(grid + (size_t)tile0 * HW);
    const float4* gb = reinterpret_cast<const float4*>(grid + (size_t)(tile0 + 1) * HW);

    // Front-batch 8 LDG.128 for MLP=8
    float4 a0 = ga[tid];
    float4 a1 = ga[tid + 256];
    float4 a2 = ga[tid + 512];
    float4 a3 = ga[tid + 768];
    float4 b0 = gb[tid];
    float4 b1 = gb[tid + 256];
    float4 b2 = gb[tid + 512];
    float4 b3 = gb[tid + 768];

    float ma = fminf(fminf(a0.x, a0.y), fminf(a0.z, a0.w));
    ma = fminf(ma, fminf(fminf(a1.x, a1.y), fminf(a1.z, a1.w)));
    ma = fminf(ma, fminf(fminf(a2.x, a2.y), fminf(a2.z, a2.w)));
    ma = fminf(ma, fminf(fminf(a3.x, a3.y), fminf(a3.z, a3.w)));

    float mb = fminf(fminf(b0.x, b0.y), fminf(b0.z, b0.w));
    mb = fminf(mb, fminf(fminf(b1.x, b1.y), fminf(b1.z, b1.w)));
    mb = fminf(mb, fminf(fminf(b2.x, b2.y), fminf(b2.z, b2.w)));
    mb = fminf(mb, fminf(fminf(b3.x, b3.y), fminf(b3.z, b3.w)));

    // two parallel warp reductions
    #pragma unroll
    for (int o = 16; o > 0; o >>= 1) {
        ma = fminf(ma, __shfl_xor_sync(0xFFFFFFFFu, ma, o));
        mb = fminf(mb, __shfl_xor_sync(0xFFFFFFFFu, mb, o));
    }

    __shared__ float smin[2][8];
    if ((tid & 31) == 0) {
        smin[0][tid >> 5] = ma;
        smin[1][tid >> 5] = mb;
    }
    __syncthreads();

    // 4 output threads: (tile_sel, b) = (tid>>1, tid&1)
    if (tid < 4) {
        const int tsel = tid >> 1;
        const int b    = tid & 1;

        float mm = smin[tsel][0];
        #pragma unroll
        for (int i = 1; i < 8; i++) mm = fminf(mm, smin[tsel][i]);
        const float dist = mm + 1.0f;   // min over (grid+1) == min(grid)+1

        const int tile = tile0 + tsel;
        const int idx  = b * HW + tile;

        const float p = preds[idx];
        const float g = gts[idx];

        const float loss = -g * logf(p + EPS_F)
                           - (1.0f - g) * logf(fabsf(1.0f - p - EPS_F));

        const float pred_mask = p + (1.0f - p) * BIG_F;
        const float gt_th     = g + (1.0f - g) * BIG_F;

        out[idx]           = loss;
        out[BHW + idx]     = gt_th * dist * p;
        out[2 * BHW + idx] = g * dist * pred_mask;
    }
}

extern "C" void kernel_launch(void* const* d_in, const int* in_sizes, int n_in,
                              void* d_out, int out_size)
{
    const float* preds = (const float*)d_in[0];
    const float* gts   = (const float*)d_in[1];
    const float* grid  = (const float*)d_in[2];
    float* out = (float*)d_out;

    project_loss_kernel<<<HW / TILES_PER_BLOCK, 256>>>(preds, gts, grid, out);
}